// round 11
// baseline (speedup 1.0000x reference)
#include <cuda_runtime.h>
#include <cuda_bf16.h>
#include <cstdint>

#define N_NODES 100000
#define N_EDGES 1600000
#define IN_DIM 1433
#define HID_DIM 128
#define EMB_DIM 64
#define KPAD 1472          // 23 * 64
#define KCHUNKS 23

// ---------------- scratch (static device globals; no cudaMalloc allowed) ----------------
__device__ float g_g1[(size_t)N_NODES * HID_DIM];
__device__ __nv_bfloat16 g_h1h[(size_t)N_NODES * HID_DIM];
__device__ __nv_bfloat16 g_h1l[(size_t)N_NODES * HID_DIM];
__device__ float g_g2[(size_t)N_NODES * EMB_DIM];
__device__ int   g_indeg[N_NODES];
__device__ int   g_rowptr[N_NODES + 1];
__device__ int   g_cursor[N_NODES];
__device__ int   g_col[N_EDGES];
__device__ float g_dinv[N_NODES];
__device__ __nv_bfloat16 g_Wt_hi[HID_DIM * KPAD];            // W1^T bf16-high, [128][KPAD]
__device__ __align__(16) signed char g_W8h[HID_DIM * KPAD];  // round(bh*768)
__device__ __align__(16) signed char g_W8l[HID_DIM * KPAD];  // round(bl*196608)
__device__ __nv_bfloat16 g_W2t_hi[EMB_DIM * HID_DIM];        // W2^T split, [64][128]
__device__ __nv_bfloat16 g_W2t_lo[EMB_DIM * HID_DIM];

// correction scale: (16 * 196608) == (4096 * 768) == 3145728
#define CORR_INV (1.0f / 3145728.0f)

// ---------------- portable PTX helpers ----------------
__device__ __forceinline__ uint32_t smem_u32(const void* p) {
    uint32_t a;
    asm("{ .reg .u64 t; cvta.to.shared.u64 t, %1; cvt.u32.u64 %0, t; }" : "=r"(a) : "l"(p));
    return a;
}
__device__ __forceinline__ void ldsm_x4(uint32_t& r0, uint32_t& r1, uint32_t& r2, uint32_t& r3,
                                        uint32_t addr) {
    asm volatile("ldmatrix.sync.aligned.m8n8.x4.shared.b16 {%0,%1,%2,%3}, [%4];"
                 : "=r"(r0), "=r"(r1), "=r"(r2), "=r"(r3) : "r"(addr));
}
__device__ __forceinline__ void mma_bf16(float* d, const uint32_t* a, const uint32_t* b) {
    asm volatile(
        "mma.sync.aligned.m16n8k16.row.col.f32.bf16.bf16.f32 "
        "{%0,%1,%2,%3}, {%4,%5,%6,%7}, {%8,%9}, {%0,%1,%2,%3};"
        : "+f"(d[0]), "+f"(d[1]), "+f"(d[2]), "+f"(d[3])
        : "r"(a[0]), "r"(a[1]), "r"(a[2]), "r"(a[3]), "r"(b[0]), "r"(b[1]));
}
__device__ __forceinline__ void mma_s8(int* d, const uint32_t* a, const uint32_t* b) {
    asm volatile(
        "mma.sync.aligned.m16n8k32.row.col.s32.s8.s8.s32 "
        "{%0,%1,%2,%3}, {%4,%5,%6,%7}, {%8,%9}, {%0,%1,%2,%3};"
        : "+r"(d[0]), "+r"(d[1]), "+r"(d[2]), "+r"(d[3])
        : "r"(a[0]), "r"(a[1]), "r"(a[2]), "r"(a[3]), "r"(b[0]), "r"(b[1]));
}
__device__ __forceinline__ void cp16(uint32_t dst, const void* src, bool valid) {
    int sz = valid ? 16 : 0;
    asm volatile("cp.async.cg.shared.global [%0], [%1], 16, %2;"
                 :: "r"(dst), "l"(src), "r"(sz) : "memory");
}
__device__ __forceinline__ void cp4(uint32_t dst, const void* src, bool valid) {
    int sz = valid ? 4 : 0;
    asm volatile("cp.async.ca.shared.global [%0], [%1], 4, %2;"
                 :: "r"(dst), "l"(src), "r"(sz) : "memory");
}
__device__ __forceinline__ void cp_commit() { asm volatile("cp.async.commit_group;" ::: "memory"); }
__device__ __forceinline__ void cp_wait_all() { asm volatile("cp.async.wait_group 0;" ::: "memory"); }
__device__ __forceinline__ uint32_t pkh(__nv_bfloat16 a, __nv_bfloat16 b) {
    __nv_bfloat162 t; t.x = a; t.y = b;
    return *(uint32_t*)&t;
}
__device__ __forceinline__ int q8(float x) {
    int t = __float2int_rn(x);
    return max(-127, min(127, t));
}
__device__ __forceinline__ uint32_t pk8(int a0, int a1, int a2, int a3) {
    return (uint32_t)(a0 & 255) | ((uint32_t)(a1 & 255) << 8) |
           ((uint32_t)(a2 & 255) << 16) | ((uint32_t)(a3 & 255) << 24);
}

// ---------------- CSR build ----------------
__global__ void k_zero_indeg() {
    int i = blockIdx.x * blockDim.x + threadIdx.x;
    if (i < N_NODES) g_indeg[i] = 0;
}
__global__ void k_hist(const int4* __restrict__ dst4) {
    int i = blockIdx.x * blockDim.x + threadIdx.x;
    if (i < N_EDGES / 4) {
        int4 d = __ldg(dst4 + i);
        atomicAdd(&g_indeg[d.x], 1);
        atomicAdd(&g_indeg[d.y], 1);
        atomicAdd(&g_indeg[d.z], 1);
        atomicAdd(&g_indeg[d.w], 1);
    }
}
__global__ void k_scan() {
    __shared__ int wsum[32];
    __shared__ int s_carry;
    const int tid = threadIdx.x, lane = tid & 31, wid = tid >> 5;
    if (tid == 0) s_carry = 0;
    __syncthreads();
    for (int base = 0; base < N_NODES; base += 1024) {
        int i = base + tid;
        int v = (i < N_NODES) ? g_indeg[i] : 0;
        int x = v;
        #pragma unroll
        for (int off = 1; off < 32; off <<= 1) {
            int t = __shfl_up_sync(0xFFFFFFFF, x, off);
            if (lane >= off) x += t;
        }
        if (lane == 31) wsum[wid] = x;
        __syncthreads();
        if (wid == 0) {
            int w = wsum[lane];
            #pragma unroll
            for (int off = 1; off < 32; off <<= 1) {
                int t = __shfl_up_sync(0xFFFFFFFF, w, off);
                if (lane >= off) w += t;
            }
            wsum[lane] = w;
        }
        __syncthreads();
        int incl = x + (wid > 0 ? wsum[wid - 1] : 0) + s_carry;
        if (i < N_NODES) {
            int rp = incl - v;
            g_rowptr[i] = rp;
            g_cursor[i] = rp;
            g_dinv[i]   = rsqrtf((float)(v + 1));
        }
        __syncthreads();
        if (tid == 0) s_carry += wsum[31];
        __syncthreads();
    }
    if (tid == 0) g_rowptr[N_NODES] = N_EDGES;
}
__global__ void k_fill(const int4* __restrict__ src4, const int4* __restrict__ dst4) {
    int i = blockIdx.x * blockDim.x + threadIdx.x;
    if (i < N_EDGES / 4) {
        int4 s = __ldg(src4 + i);
        int4 d = __ldg(dst4 + i);
        g_col[atomicAdd(&g_cursor[d.x], 1)] = s.x;
        g_col[atomicAdd(&g_cursor[d.y], 1)] = s.y;
        g_col[atomicAdd(&g_cursor[d.z], 1)] = s.z;
        g_col[atomicAdd(&g_cursor[d.w], 1)] = s.w;
    }
}

// ---------------- weight transpose + split (bf16 hi + int8 hi/lo) ----------------
__global__ void k_convert_W(const float* __restrict__ W1) {
    __shared__ float t[32][33];
    int k0 = blockIdx.x * 32, n0 = blockIdx.y * 32;
    #pragma unroll
    for (int j = threadIdx.y; j < 32; j += 8) {
        int k = k0 + j, n = n0 + threadIdx.x;
        t[j][threadIdx.x] = (k < IN_DIM) ? __ldg(W1 + (size_t)k * HID_DIM + n) : 0.f;
    }
    __syncthreads();
    #pragma unroll
    for (int j = threadIdx.y; j < 32; j += 8) {
        int n = n0 + j, k = k0 + threadIdx.x;
        float v = t[threadIdx.x][j];
        __nv_bfloat16 h = __float2bfloat16(v);
        float hf = __bfloat162float(h);
        float lo = v - hf;
        size_t o = (size_t)n * KPAD + k;
        g_Wt_hi[o] = h;
        g_W8h[o] = (signed char)q8(hf * 768.f);
        g_W8l[o] = (signed char)q8(lo * 196608.f);
    }
}
__global__ void k_convert_W2(const float* __restrict__ W2) {
    int idx = blockIdx.x * blockDim.x + threadIdx.x;
    if (idx < EMB_DIM * HID_DIM) {
        int n = idx / HID_DIM, k = idx % HID_DIM;
        float v = W2[(size_t)k * EMB_DIM + n];
        __nv_bfloat16 h = __float2bfloat16(v);
        g_W2t_hi[idx] = h;
        g_W2t_lo[idx] = __float2bfloat16(v - __bfloat162float(h));
    }
}

// ---------------- GEMM1: C[M x 128] = X @ W1  (bf16 main + int8 corrections) ----------------
// acc_f += ah*bh (bf16 k16); acc_i += ah8*bl8 + al8*bh8 (s8 k32); C = acc_f + acc_i/3145728
#define SM_STRIDE 72          // bf16 elems per row (144B)
#define S8_STRIDE 80          // bytes per s8 row (40 b16 units) — conflict-free ldsm
#define G1_XF0  0
#define G1_XF1  32768
#define G1_AH   65536         /* 18432 */
#define G1_A8H  83968         /* 10240 */
#define G1_A8L  94208         /* 10240 */
#define G1_BS0  104448
#define G1_BSTG 38912         /* BH 18432 + B8H 10240 + B8L 10240 */
#define G1_SMEM (G1_BS0 + 2 * G1_BSTG)   /* 182272 */
#define G1_THREADS 512

__global__ __launch_bounds__(G1_THREADS)
void gemm1_hmma(const float* __restrict__ X, float* __restrict__ C) {
    extern __shared__ char smem[];
    const uint32_t sbase = smem_u32(smem);
    const int tid = threadIdx.x, lane = tid & 31, wid = tid >> 5;
    const int wm = wid >> 2, wn = wid & 3;   // 4 x 4 warps, warp tile 32 x 32
    const int mbase = blockIdx.x * 128;

    const int a_r = (lane & 15), a_c = ((lane & 16) >> 1);
    const int b_r = ((lane & 16) >> 1) + (lane & 7), b_c = (lane & 8);

    float accf[2][4][4];
    int   acci[2][4][4];
    #pragma unroll
    for (int i = 0; i < 2; i++)
        #pragma unroll
        for (int j = 0; j < 4; j++)
            #pragma unroll
            for (int v = 0; v < 4; v++) { accf[i][j][v] = 0.f; acci[i][j][v] = 0; }

    auto issue = [&](int kc, int buf) {
        const int k0 = kc * 64;
        uint32_t xdst = sbase + (buf ? G1_XF1 : G1_XF0);
        #pragma unroll
        for (int i = tid; i < 8192; i += G1_THREADS) {
            int r = i >> 6, kp = i & 63;
            int gr = mbase + r, gk = k0 + kp;
            cp4(xdst + (uint32_t)i * 4, X + (size_t)gr * IN_DIM + gk,
                (gr < N_NODES) && (gk < IN_DIM));
        }
        uint32_t bh = sbase + G1_BS0 + buf * G1_BSTG;
        uint32_t b8h = bh + 18432, b8l = bh + 28672;
        // BH bf16: 128 rows x 128B = 1024 cp16
        #pragma unroll
        for (int i = tid; i < 1024; i += G1_THREADS) {
            int n = i >> 3, c8 = (i & 7) * 8;
            cp16(bh + (uint32_t)(n * SM_STRIDE + c8) * 2,
                 g_Wt_hi + (size_t)n * KPAD + k0 + c8, true);
        }
        // B8H/B8L s8: 128 rows x 64B = 512 cp16 each (tid < 512 == all threads once)
        {
            int n = tid >> 2, c16 = (tid & 3) * 16;
            size_t soff = (size_t)n * KPAD + k0 + c16;
            cp16(b8h + (uint32_t)(n * S8_STRIDE + c16), g_W8h + soff, true);
            cp16(b8l + (uint32_t)(n * S8_STRIDE + c16), g_W8l + soff, true);
        }
    };

    issue(0, 0);
    cp_commit();

    for (int kc = 0; kc < KCHUNKS; kc++) {
        const int buf = kc & 1;
        cp_wait_all();
        __syncthreads();
        if (kc + 1 < KCHUNKS) { issue(kc + 1, buf ^ 1); cp_commit(); }

        // ---- split fp32 -> bf16 hi + s8 (ah*16) + s8 (al*4096) ----
        {
            const float4* xf = (const float4*)(smem + (buf ? G1_XF1 : G1_XF0));
            #pragma unroll
            for (int i = tid; i < 2048; i += G1_THREADS) {
                float4 v = xf[i];
                int r = i >> 4, kp4 = (i & 15) * 4;
                __nv_bfloat16 h0 = __float2bfloat16(v.x), h1 = __float2bfloat16(v.y);
                __nv_bfloat16 h2 = __float2bfloat16(v.z), h3 = __float2bfloat16(v.w);
                float f0 = __bfloat162float(h0), f1 = __bfloat162float(h1);
                float f2 = __bfloat162float(h2), f3 = __bfloat162float(h3);
                float l0 = v.x - f0, l1 = v.y - f1, l2 = v.z - f2, l3 = v.w - f3;
                uint32_t off = (uint32_t)(r * SM_STRIDE + kp4) * 2;
                *(uint2*)(smem + G1_AH + off) = make_uint2(pkh(h0, h1), pkh(h2, h3));
                uint32_t pa = pk8(q8(f0 * 16.f), q8(f1 * 16.f), q8(f2 * 16.f), q8(f3 * 16.f));
                uint32_t pc = pk8(q8(l0 * 4096.f), q8(l1 * 4096.f),
                                  q8(l2 * 4096.f), q8(l3 * 4096.f));
                *(uint32_t*)(smem + G1_A8H + r * S8_STRIDE + kp4) = pa;
                *(uint32_t*)(smem + G1_A8L + r * S8_STRIDE + kp4) = pc;
            }
        }
        __syncthreads();

        const uint32_t BH  = sbase + G1_BS0 + buf * G1_BSTG;
        const uint32_t B8H = BH + 18432, B8L = BH + 28672;
        // ---- main product: bf16, 4 k-steps of 16 ----
        #pragma unroll
        for (int ks = 0; ks < 4; ks++) {
            const int kk = ks * 16;
            uint32_t ah[2][4], bhf[4][2];
            #pragma unroll
            for (int mt = 0; mt < 2; mt++) {
                uint32_t ea = (uint32_t)((wm * 32 + mt * 16 + a_r) * SM_STRIDE + kk + a_c) * 2;
                ldsm_x4(ah[mt][0], ah[mt][1], ah[mt][2], ah[mt][3], sbase + G1_AH + ea);
            }
            #pragma unroll
            for (int pr = 0; pr < 2; pr++) {
                uint32_t eb = (uint32_t)((wn * 32 + pr * 16 + b_r) * SM_STRIDE + kk + b_c) * 2;
                ldsm_x4(bhf[2*pr][0], bhf[2*pr][1], bhf[2*pr+1][0], bhf[2*pr+1][1], BH + eb);
            }
            #pragma unroll
            for (int mt = 0; mt < 2; mt++)
                #pragma unroll
                for (int nt = 0; nt < 4; nt++)
                    mma_bf16(accf[mt][nt], ah[mt], bhf[nt]);
        }
        // ---- corrections: s8 k32, 2 k-steps of 32 bytes (16 b16-units) ----
        #pragma unroll
        for (int kss = 0; kss < 2; kss++) {
            const int ku = kss * 16;   // b16 units
            uint32_t a8h[2][4], a8l[2][4], b8h[4][2], b8l[4][2];
            #pragma unroll
            for (int mt = 0; mt < 2; mt++) {
                uint32_t ea = (uint32_t)((wm * 32 + mt * 16 + a_r) * S8_STRIDE + (ku + a_c) * 2);
                ldsm_x4(a8h[mt][0], a8h[mt][1], a8h[mt][2], a8h[mt][3], sbase + G1_A8H + ea);
                ldsm_x4(a8l[mt][0], a8l[mt][1], a8l[mt][2], a8l[mt][3], sbase + G1_A8L + ea);
            }
            #pragma unroll
            for (int pr = 0; pr < 2; pr++) {
                uint32_t eb = (uint32_t)((wn * 32 + pr * 16 + b_r) * S8_STRIDE + (ku + b_c) * 2);
                ldsm_x4(b8h[2*pr][0], b8h[2*pr][1], b8h[2*pr+1][0], b8h[2*pr+1][1], B8H + eb);
                ldsm_x4(b8l[2*pr][0], b8l[2*pr][1], b8l[2*pr+1][0], b8l[2*pr+1][1], B8L + eb);
            }
            #pragma unroll
            for (int mt = 0; mt < 2; mt++)
                #pragma unroll
                for (int nt = 0; nt < 4; nt++) {
                    mma_s8(acci[mt][nt], a8h[mt], b8l[nt]);   // ah * bl (scaled)
                    mma_s8(acci[mt][nt], a8l[mt], b8h[nt]);   // al * bh (scaled)
                }
        }
        __syncthreads();
    }

    const int g = lane >> 2, q = lane & 3;
    #pragma unroll
    for (int mt = 0; mt < 2; mt++) {
        int r0 = mbase + wm * 32 + mt * 16 + g;
        int r1 = r0 + 8;
        #pragma unroll
        for (int nt = 0; nt < 4; nt++) {
            int col = wn * 32 + nt * 8 + q * 2;
            if (r0 < N_NODES) {
                float v0 = accf[mt][nt][0] + (float)acci[mt][nt][0] * CORR_INV;
                float v1 = accf[mt][nt][1] + (float)acci[mt][nt][1] * CORR_INV;
                *(float2*)(C + (size_t)r0 * HID_DIM + col) = make_float2(v0, v1);
            }
            if (r1 < N_NODES) {
                float v2 = accf[mt][nt][2] + (float)acci[mt][nt][2] * CORR_INV;
                float v3 = accf[mt][nt][3] + (float)acci[mt][nt][3] * CORR_INV;
                *(float2*)(C + (size_t)r1 * HID_DIM + col) = make_float2(v2, v3);
            }
        }
    }
}

// ---------------- GEMM2: g2[M x 64] = h1 @ W2 (K=128 single tile, no dinv) ----------------
#define SM2_STRIDE 136
#define G2_AH 0
#define G2_AL (128 * SM2_STRIDE * 2)
#define G2_BH (2 * 128 * SM2_STRIDE * 2)
#define G2_BL (G2_BH + 64 * SM2_STRIDE * 2)
#define G2_SMEM (G2_BL + 64 * SM2_STRIDE * 2)

__global__ __launch_bounds__(256)
void gemm2_hmma(float* __restrict__ C) {
    extern __shared__ char smem[];
    const uint32_t sbase = smem_u32(smem);
    const int tid = threadIdx.x, lane = tid & 31, wid = tid >> 5;
    const int wm = wid >> 1, wn = wid & 1;
    const int mbase = blockIdx.x * 128;

    const int a_r = (lane & 15), a_c = ((lane & 16) >> 1);
    const int b_r = ((lane & 16) >> 1) + (lane & 7), b_c = (lane & 8);

    #pragma unroll
    for (int i = tid; i < 2048; i += 256) {
        int r = i >> 4, c8 = (i & 15) * 8;
        int gr = mbase + r;
        bool ok = gr < N_NODES;
        uint32_t doff = (uint32_t)(r * SM2_STRIDE + c8) * 2;
        size_t soff = (size_t)gr * HID_DIM + c8;
        cp16(sbase + G2_AH + doff, g_h1h + soff, ok);
        cp16(sbase + G2_AL + doff, g_h1l + soff, ok);
    }
    #pragma unroll
    for (int i = tid; i < 1024; i += 256) {
        int n = i >> 4, c8 = (i & 15) * 8;
        uint32_t doff = (uint32_t)(n * SM2_STRIDE + c8) * 2;
        size_t soff = (size_t)n * HID_DIM + c8;
        cp16(sbase + G2_BH + doff, g_W2t_hi + soff, true);
        cp16(sbase + G2_BL + doff, g_W2t_lo + soff, true);
    }
    cp_commit();
    cp_wait_all();
    __syncthreads();

    float acc[2][4][4];
    #pragma unroll
    for (int i = 0; i < 2; i++)
        #pragma unroll
        for (int j = 0; j < 4; j++)
            #pragma unroll
            for (int v = 0; v < 4; v++) acc[i][j][v] = 0.f;

    #pragma unroll
    for (int ks = 0; ks < 8; ks++) {
        const int kk = ks * 16;
        uint32_t ah[2][4], al[2][4], bhf[4][2], blf[4][2];
        #pragma unroll
        for (int mt = 0; mt < 2; mt++) {
            uint32_t ea = (uint32_t)((wm * 32 + mt * 16 + a_r) * SM2_STRIDE + kk + a_c) * 2;
            ldsm_x4(ah[mt][0], ah[mt][1], ah[mt][2], ah[mt][3], sbase + G2_AH + ea);
            ldsm_x4(al[mt][0], al[mt][1], al[mt][2], al[mt][3], sbase + G2_AL + ea);
        }
        #pragma unroll
        for (int pr = 0; pr < 2; pr++) {
            uint32_t eb = (uint32_t)((wn * 32 + pr * 16 + b_r) * SM2_STRIDE + kk + b_c) * 2;
            ldsm_x4(bhf[2*pr][0], bhf[2*pr][1], bhf[2*pr+1][0], bhf[2*pr+1][1], sbase + G2_BH + eb);
            ldsm_x4(blf[2*pr][0], blf[2*pr][1], blf[2*pr+1][0], blf[2*pr+1][1], sbase + G2_BL + eb);
        }
        #pragma unroll
        for (int mt = 0; mt < 2; mt++)
            #pragma unroll
            for (int nt = 0; nt < 4; nt++) {
                mma_bf16(acc[mt][nt], ah[mt], bhf[nt]);
                mma_bf16(acc[mt][nt], ah[mt], blf[nt]);
                mma_bf16(acc[mt][nt], al[mt], bhf[nt]);
            }
    }

    const int g = lane >> 2, q = lane & 3;
    #pragma unroll
    for (int mt = 0; mt < 2; mt++) {
        int r0 = mbase + wm * 32 + mt * 16 + g;
        int r1 = r0 + 8;
        #pragma unroll
        for (int nt = 0; nt < 4; nt++) {
            int col = wn * 32 + nt * 8 + q * 2;
            if (r0 < N_NODES)
                *(float2*)(C + (size_t)r0 * EMB_DIM + col) =
                    make_float2(acc[mt][nt][0], acc[mt][nt][1]);
            if (r1 < N_NODES)
                *(float2*)(C + (size_t)r1 * EMB_DIM + col) =
                    make_float2(acc[mt][nt][2], acc[mt][nt][3]);
        }
    }
}

// ---------------- CSR gather aggregation: warp per node, dinv folded here ----------------
__global__ __launch_bounds__(256)
void aggregate1(const float* __restrict__ g, const float* __restrict__ bias) {
    const int lane = threadIdx.x & 31, wid = threadIdx.x >> 5;
    const int node = blockIdx.x * 8 + wid;
    if (node >= N_NODES) return;
    const float4* g4 = (const float4*)g;

    float di = g_dinv[node];
    float4 v = __ldg(g4 + (size_t)node * 32 + lane);
    float4 s = make_float4(di * v.x, di * v.y, di * v.z, di * v.w);
    int e = g_rowptr[node], end = g_rowptr[node + 1];
    for (; e + 4 <= end; e += 4) {
        int c0 = g_col[e], c1 = g_col[e+1], c2 = g_col[e+2], c3 = g_col[e+3];
        float d0 = __ldg(g_dinv + c0), d1 = __ldg(g_dinv + c1),
              d2 = __ldg(g_dinv + c2), d3 = __ldg(g_dinv + c3);
        float4 v0 = __ldg(g4 + (size_t)c0 * 32 + lane);
        float4 v1 = __ldg(g4 + (size_t)c1 * 32 + lane);
        float4 v2 = __ldg(g4 + (size_t)c2 * 32 + lane);
        float4 v3 = __ldg(g4 + (size_t)c3 * 32 + lane);
        s.x += d0 * v0.x + d1 * v1.x + d2 * v2.x + d3 * v3.x;
        s.y += d0 * v0.y + d1 * v1.y + d2 * v2.y + d3 * v3.y;
        s.z += d0 * v0.z + d1 * v1.z + d2 * v2.z + d3 * v3.z;
        s.w += d0 * v0.w + d1 * v1.w + d2 * v2.w + d3 * v3.w;
    }
    for (; e < end; e++) {
        int c = g_col[e];
        float d = __ldg(g_dinv + c);
        float4 w = __ldg(g4 + (size_t)c * 32 + lane);
        s.x += d * w.x; s.y += d * w.y; s.z += d * w.z; s.w += d * w.w;
    }
    float4 b = __ldg((const float4*)bias + lane);
    float o0 = fmaxf(di * s.x + b.x, 0.f), o1 = fmaxf(di * s.y + b.y, 0.f);
    float o2 = fmaxf(di * s.z + b.z, 0.f), o3 = fmaxf(di * s.w + b.w, 0.f);
    __nv_bfloat16 h0 = __float2bfloat16(o0), h1 = __float2bfloat16(o1),
                  h2 = __float2bfloat16(o2), h3 = __float2bfloat16(o3);
    uint2 H = make_uint2(pkh(h0, h1), pkh(h2, h3));
    uint2 L = make_uint2(
        pkh(__float2bfloat16(o0 - __bfloat162float(h0)),
            __float2bfloat16(o1 - __bfloat162float(h1))),
        pkh(__float2bfloat16(o2 - __bfloat162float(h2)),
            __float2bfloat16(o3 - __bfloat162float(h3))));
    ((uint2*)g_h1h)[(size_t)node * 32 + lane] = H;
    ((uint2*)g_h1l)[(size_t)node * 32 + lane] = L;
}
__global__ __launch_bounds__(256)
void aggregate2(const float* __restrict__ g, const float* __restrict__ bias,
                float* __restrict__ out) {
    const int lane = threadIdx.x & 31, wid = threadIdx.x >> 5;
    const int node = blockIdx.x * 8 + wid;
    if (node >= N_NODES) return;
    const float2* g2 = (const float2*)g;

    float di = g_dinv[node];
    float2 v = __ldg(g2 + (size_t)node * 32 + lane);
    float2 s = make_float2(di * v.x, di * v.y);
    int e = g_rowptr[node], end = g_rowptr[node + 1];
    for (; e + 4 <= end; e += 4) {
        int c0 = g_col[e], c1 = g_col[e+1], c2 = g_col[e+2], c3 = g_col[e+3];
        float d0 = __ldg(g_dinv + c0), d1 = __ldg(g_dinv + c1),
              d2 = __ldg(g_dinv + c2), d3 = __ldg(g_dinv + c3);
        float2 v0 = __ldg(g2 + (size_t)c0 * 32 + lane);
        float2 v1 = __ldg(g2 + (size_t)c1 * 32 + lane);
        float2 v2 = __ldg(g2 + (size_t)c2 * 32 + lane);
        float2 v3 = __ldg(g2 + (size_t)c3 * 32 + lane);
        s.x += d0 * v0.x + d1 * v1.x + d2 * v2.x + d3 * v3.x;
        s.y += d0 * v0.y + d1 * v1.y + d2 * v2.y + d3 * v3.y;
    }
    for (; e < end; e++) {
        int c = g_col[e];
        float d = __ldg(g_dinv + c);
        float2 w = __ldg(g2 + (size_t)c * 32 + lane);
        s.x += d * w.x; s.y += d * w.y;
    }
    float2 b = __ldg((const float2*)bias + lane);
    ((float2*)out)[(size_t)node * 32 + lane] = make_float2(di * s.x + b.x, di * s.y + b.y);
}

// ---------------- launch ----------------
extern "C" void kernel_launch(void* const* d_in, const int* in_sizes, int n_in,
                              void* d_out, int out_size) {
    const float* x  = (const float*)d_in[0];
    const int*   ei = (const int*)  d_in[1];
    const float* W1 = (const float*)d_in[2];
    const float* b1 = (const float*)d_in[3];
    const float* W2 = (const float*)d_in[4];
    const float* b2 = (const float*)d_in[5];
    float* out = (float*)d_out;

    const int4* src4 = (const int4*)ei;
    const int4* dst4 = (const int4*)(ei + N_EDGES);

    float *p_g1 = nullptr, *p_g2 = nullptr;
    cudaGetSymbolAddress((void**)&p_g1, g_g1);
    cudaGetSymbolAddress((void**)&p_g2, g_g2);

    static cudaStream_t s2 = nullptr;
    static cudaEvent_t ev_fork = nullptr, ev_join = nullptr;
    static bool init_done = false;
    if (!init_done) {
        cudaFuncSetAttribute(gemm1_hmma, cudaFuncAttributeMaxDynamicSharedMemorySize, G1_SMEM);
        cudaFuncSetAttribute(gemm2_hmma, cudaFuncAttributeMaxDynamicSharedMemorySize, G2_SMEM);
        cudaStreamCreateWithFlags(&s2, cudaStreamNonBlocking);
        cudaEventCreateWithFlags(&ev_fork, cudaEventDisableTiming);
        cudaEventCreateWithFlags(&ev_join, cudaEventDisableTiming);
        init_done = true;
    }

    // fork: CSR build on side stream, concurrent with converts + gemm1
    cudaEventRecord(ev_fork, 0);
    cudaStreamWaitEvent(s2, ev_fork, 0);

    k_zero_indeg<<<(N_NODES + 255) / 256, 256, 0, s2>>>();
    k_hist<<<(N_EDGES / 4 + 255) / 256, 256, 0, s2>>>(dst4);
    k_scan<<<1, 1024, 0, s2>>>();
    k_fill<<<(N_EDGES / 4 + 255) / 256, 256, 0, s2>>>(src4, dst4);
    cudaEventRecord(ev_join, s2);

    k_convert_W<<<dim3(KPAD / 32, HID_DIM / 32), dim3(32, 8)>>>(W1);
    k_convert_W2<<<(EMB_DIM * HID_DIM + 255) / 256, 256>>>(W2);

    const int mblocks = (N_NODES + 127) / 128;
    gemm1_hmma<<<mblocks, G1_THREADS, G1_SMEM>>>(x, p_g1);

    // join: aggregation needs CSR + dinv
    cudaStreamWaitEvent(0, ev_join, 0);
    aggregate1<<<(N_NODES + 7) / 8, 256>>>(p_g1, b1);
    gemm2_hmma<<<mblocks, 256, G2_SMEM>>>(p_g2);
    aggregate2<<<(N_NODES + 7) / 8, 256>>>(p_g2, b2, out);
}

// round 12
// speedup vs baseline: 1.8037x; 1.8037x over previous
#include <cuda_runtime.h>
#include <cuda_bf16.h>
#include <cstdint>

#define N_NODES 100000
#define N_EDGES 1600000
#define IN_DIM 1433
#define HID_DIM 128
#define EMB_DIM 64
#define KPAD 1472          // 23 * 64
#define KCHUNKS 23

// ---------------- scratch (static device globals; no cudaMalloc allowed) ----------------
__device__ float g_g1[(size_t)N_NODES * HID_DIM];
__device__ __nv_bfloat16 g_h1h[(size_t)N_NODES * HID_DIM];
__device__ __nv_bfloat16 g_h1l[(size_t)N_NODES * HID_DIM];
__device__ float g_g2[(size_t)N_NODES * EMB_DIM];
__device__ int   g_indeg[N_NODES];
__device__ int   g_rowptr[N_NODES + 1];
__device__ int   g_cursor[N_NODES];
__device__ int   g_col[N_EDGES];
__device__ float g_dinv[N_NODES];
__device__ __nv_bfloat16 g_Wt_hi[HID_DIM * KPAD];    // W1^T split-high, [128][KPAD]
__device__ __nv_bfloat16 g_Wt_lo[HID_DIM * KPAD];
__device__ __nv_bfloat16 g_W2t_hi[EMB_DIM * HID_DIM]; // W2^T split, [64][128]
__device__ __nv_bfloat16 g_W2t_lo[EMB_DIM * HID_DIM];

// ---------------- portable PTX helpers ----------------
__device__ __forceinline__ uint32_t smem_u32(const void* p) {
    uint32_t a;
    asm("{ .reg .u64 t; cvta.to.shared.u64 t, %1; cvt.u32.u64 %0, t; }" : "=r"(a) : "l"(p));
    return a;
}
__device__ __forceinline__ void ldsm_x4(uint32_t& r0, uint32_t& r1, uint32_t& r2, uint32_t& r3,
                                        uint32_t addr) {
    asm volatile("ldmatrix.sync.aligned.m8n8.x4.shared.b16 {%0,%1,%2,%3}, [%4];"
                 : "=r"(r0), "=r"(r1), "=r"(r2), "=r"(r3) : "r"(addr));
}
__device__ __forceinline__ void mma_bf16(float* d, const uint32_t* a, const uint32_t* b) {
    asm volatile(
        "mma.sync.aligned.m16n8k16.row.col.f32.bf16.bf16.f32 "
        "{%0,%1,%2,%3}, {%4,%5,%6,%7}, {%8,%9}, {%0,%1,%2,%3};"
        : "+f"(d[0]), "+f"(d[1]), "+f"(d[2]), "+f"(d[3])
        : "r"(a[0]), "r"(a[1]), "r"(a[2]), "r"(a[3]), "r"(b[0]), "r"(b[1]));
}
__device__ __forceinline__ void cp16(uint32_t dst, const void* src, bool valid) {
    int sz = valid ? 16 : 0;
    asm volatile("cp.async.cg.shared.global [%0], [%1], 16, %2;"
                 :: "r"(dst), "l"(src), "r"(sz) : "memory");
}
__device__ __forceinline__ void cp4(uint32_t dst, const void* src, bool valid) {
    int sz = valid ? 4 : 0;
    asm volatile("cp.async.ca.shared.global [%0], [%1], 4, %2;"
                 :: "r"(dst), "l"(src), "r"(sz) : "memory");
}
__device__ __forceinline__ void cp_commit() { asm volatile("cp.async.commit_group;" ::: "memory"); }
__device__ __forceinline__ void cp_wait_all() { asm volatile("cp.async.wait_group 0;" ::: "memory"); }
__device__ __forceinline__ uint32_t pkh(__nv_bfloat16 a, __nv_bfloat16 b) {
    __nv_bfloat162 t; t.x = a; t.y = b;
    return *(uint32_t*)&t;
}

// ---------------- CSR build ----------------
__global__ void k_zero_indeg() {
    int i = blockIdx.x * blockDim.x + threadIdx.x;
    if (i < N_NODES) g_indeg[i] = 0;
}
__global__ void k_hist(const int4* __restrict__ dst4) {
    int i = blockIdx.x * blockDim.x + threadIdx.x;
    if (i < N_EDGES / 4) {
        int4 d = __ldg(dst4 + i);
        atomicAdd(&g_indeg[d.x], 1);
        atomicAdd(&g_indeg[d.y], 1);
        atomicAdd(&g_indeg[d.z], 1);
        atomicAdd(&g_indeg[d.w], 1);
    }
}
__global__ void k_scan() {
    __shared__ int wsum[32];
    __shared__ int s_carry;
    const int tid = threadIdx.x, lane = tid & 31, wid = tid >> 5;
    if (tid == 0) s_carry = 0;
    __syncthreads();
    for (int base = 0; base < N_NODES; base += 1024) {
        int i = base + tid;
        int v = (i < N_NODES) ? g_indeg[i] : 0;
        int x = v;
        #pragma unroll
        for (int off = 1; off < 32; off <<= 1) {
            int t = __shfl_up_sync(0xFFFFFFFF, x, off);
            if (lane >= off) x += t;
        }
        if (lane == 31) wsum[wid] = x;
        __syncthreads();
        if (wid == 0) {
            int w = wsum[lane];
            #pragma unroll
            for (int off = 1; off < 32; off <<= 1) {
                int t = __shfl_up_sync(0xFFFFFFFF, w, off);
                if (lane >= off) w += t;
            }
            wsum[lane] = w;
        }
        __syncthreads();
        int incl = x + (wid > 0 ? wsum[wid - 1] : 0) + s_carry;
        if (i < N_NODES) {
            int rp = incl - v;
            g_rowptr[i] = rp;
            g_cursor[i] = rp;
            g_dinv[i]   = rsqrtf((float)(v + 1));
        }
        __syncthreads();
        if (tid == 0) s_carry += wsum[31];
        __syncthreads();
    }
    if (tid == 0) g_rowptr[N_NODES] = N_EDGES;
}
__global__ void k_fill(const int4* __restrict__ src4, const int4* __restrict__ dst4) {
    int i = blockIdx.x * blockDim.x + threadIdx.x;
    if (i < N_EDGES / 4) {
        int4 s = __ldg(src4 + i);
        int4 d = __ldg(dst4 + i);
        g_col[atomicAdd(&g_cursor[d.x], 1)] = s.x;
        g_col[atomicAdd(&g_cursor[d.y], 1)] = s.y;
        g_col[atomicAdd(&g_cursor[d.z], 1)] = s.z;
        g_col[atomicAdd(&g_cursor[d.w], 1)] = s.w;
    }
}

// ---------------- weight transpose + bf16 split (smem tiled) ----------------
__global__ void k_convert_W(const float* __restrict__ W1) {
    __shared__ float t[32][33];
    int k0 = blockIdx.x * 32, n0 = blockIdx.y * 32;
    #pragma unroll
    for (int j = threadIdx.y; j < 32; j += 8) {
        int k = k0 + j, n = n0 + threadIdx.x;
        t[j][threadIdx.x] = (k < IN_DIM) ? __ldg(W1 + (size_t)k * HID_DIM + n) : 0.f;
    }
    __syncthreads();
    #pragma unroll
    for (int j = threadIdx.y; j < 32; j += 8) {
        int n = n0 + j, k = k0 + threadIdx.x;
        float v = t[threadIdx.x][j];
        __nv_bfloat16 h = __float2bfloat16(v);
        size_t o = (size_t)n * KPAD + k;
        g_Wt_hi[o] = h;
        g_Wt_lo[o] = __float2bfloat16(v - __bfloat162float(h));
    }
}
__global__ void k_convert_W2(const float* __restrict__ W2) {
    int idx = blockIdx.x * blockDim.x + threadIdx.x;
    if (idx < EMB_DIM * HID_DIM) {
        int n = idx / HID_DIM, k = idx % HID_DIM;
        float v = W2[(size_t)k * EMB_DIM + n];
        __nv_bfloat16 h = __float2bfloat16(v);
        g_W2t_hi[idx] = h;
        g_W2t_lo[idx] = __float2bfloat16(v - __bfloat162float(h));
    }
}

// ---------------- GEMM1: C[M x 128] = X @ W1  (R9 pipeline + double-buffered A split) ----------------
#define SM_STRIDE 72   // bf16 elems per row (144B): conflict-free ldmatrix
#define G1_XF0 0
#define G1_XF1 32768
#define G1_AH(s) (65536 + (s) * 36864)
#define G1_AL(s) (G1_AH(s) + 18432)
#define G1_BH(s) (139264 + (s) * 36864)
#define G1_BL(s) (G1_BH(s) + 18432)
#define G1_SMEM 212992
#define G1_THREADS 512

__global__ __launch_bounds__(G1_THREADS)
void gemm1_hmma(const float* __restrict__ X, float* __restrict__ C) {
    extern __shared__ char smem[];
    const uint32_t sbase = smem_u32(smem);
    const int tid = threadIdx.x, lane = tid & 31, wid = tid >> 5;
    const int wm = wid >> 2, wn = wid & 3;   // 4 x 4 warps, warp tile 32 x 32
    const int mbase = blockIdx.x * 128;

    const int a_r = (lane & 15), a_c = ((lane & 16) >> 1);
    const int b_r = ((lane & 16) >> 1) + (lane & 7), b_c = (lane & 8);

    float acc[2][4][4];
    #pragma unroll
    for (int i = 0; i < 2; i++)
        #pragma unroll
        for (int j = 0; j < 4; j++)
            #pragma unroll
            for (int v = 0; v < 4; v++) acc[i][j][v] = 0.f;

    auto issue = [&](int kc, int buf) {
        const int k0 = kc * 64;
        uint32_t xdst = sbase + (buf ? G1_XF1 : G1_XF0);
        #pragma unroll
        for (int i = tid; i < 8192; i += G1_THREADS) {
            int r = i >> 6, kp = i & 63;
            int gr = mbase + r, gk = k0 + kp;
            cp4(xdst + (uint32_t)i * 4, X + (size_t)gr * IN_DIM + gk,
                (gr < N_NODES) && (gk < IN_DIM));
        }
        uint32_t bh = sbase + G1_BH(buf);
        uint32_t bl = sbase + G1_BL(buf);
        #pragma unroll
        for (int i = tid; i < 1024; i += G1_THREADS) {
            int n = i >> 3, c8 = (i & 7) * 8;
            uint32_t doff = (uint32_t)(n * SM_STRIDE + c8) * 2;
            size_t soff = (size_t)n * KPAD + k0 + c8;
            cp16(bh + doff, g_Wt_hi + soff, true);
            cp16(bl + doff, g_Wt_lo + soff, true);
        }
    };

    issue(0, 0);
    cp_commit();

    for (int kc = 0; kc < KCHUNKS; kc++) {
        const int buf = kc & 1;
        cp_wait_all();
        __syncthreads();   // cp.async visibility + fences all prior-iteration reads
        if (kc + 1 < KCHUNKS) { issue(kc + 1, buf ^ 1); cp_commit(); }

        // ---- split fp32 -> hi/lo bf16 into double-buffered AH/AL[buf] ----
        {
            const float4* xf = (const float4*)(smem + (buf ? G1_XF1 : G1_XF0));
            #pragma unroll
            for (int i = tid; i < 2048; i += G1_THREADS) {
                float4 v = xf[i];
                int r = i >> 4, kp4 = (i & 15) * 4;
                __nv_bfloat16 h0 = __float2bfloat16(v.x), h1 = __float2bfloat16(v.y);
                __nv_bfloat16 h2 = __float2bfloat16(v.z), h3 = __float2bfloat16(v.w);
                __nv_bfloat16 l0 = __float2bfloat16(v.x - __bfloat162float(h0));
                __nv_bfloat16 l1 = __float2bfloat16(v.y - __bfloat162float(h1));
                __nv_bfloat16 l2 = __float2bfloat16(v.z - __bfloat162float(h2));
                __nv_bfloat16 l3 = __float2bfloat16(v.w - __bfloat162float(h3));
                uint32_t off = (uint32_t)(r * SM_STRIDE + kp4) * 2;
                *(uint2*)(smem + G1_AH(buf) + off) = make_uint2(pkh(h0, h1), pkh(h2, h3));
                *(uint2*)(smem + G1_AL(buf) + off) = make_uint2(pkh(l0, l1), pkh(l2, l3));
            }
        }
        __syncthreads();   // split stores visible to all consumer warps

        const uint32_t AH = sbase + G1_AH(buf), AL = sbase + G1_AL(buf);
        const uint32_t BH = sbase + G1_BH(buf), BL = sbase + G1_BL(buf);
        #pragma unroll
        for (int ks = 0; ks < 4; ks++) {
            const int kk = ks * 16;
            uint32_t ah[2][4], al[2][4], bhf[4][2], blf[4][2];
            #pragma unroll
            for (int mt = 0; mt < 2; mt++) {
                uint32_t ea = (uint32_t)((wm * 32 + mt * 16 + a_r) * SM_STRIDE + kk + a_c) * 2;
                ldsm_x4(ah[mt][0], ah[mt][1], ah[mt][2], ah[mt][3], AH + ea);
                ldsm_x4(al[mt][0], al[mt][1], al[mt][2], al[mt][3], AL + ea);
            }
            #pragma unroll
            for (int pr = 0; pr < 2; pr++) {
                uint32_t eb = (uint32_t)((wn * 32 + pr * 16 + b_r) * SM_STRIDE + kk + b_c) * 2;
                ldsm_x4(bhf[2*pr][0], bhf[2*pr][1], bhf[2*pr+1][0], bhf[2*pr+1][1], BH + eb);
                ldsm_x4(blf[2*pr][0], blf[2*pr][1], blf[2*pr+1][0], blf[2*pr+1][1], BL + eb);
            }
            #pragma unroll
            for (int mt = 0; mt < 2; mt++)
                #pragma unroll
                for (int nt = 0; nt < 4; nt++) {
                    mma_bf16(acc[mt][nt], ah[mt], bhf[nt]);
                    mma_bf16(acc[mt][nt], ah[mt], blf[nt]);
                    mma_bf16(acc[mt][nt], al[mt], bhf[nt]);
                }
        }
        // no trailing sync: next iteration's post-wait __syncthreads fences
        // all MMA/ldsm reads of stage[buf] before any thread refills it (kc+2).
    }

    const int g = lane >> 2, q = lane & 3;
    #pragma unroll
    for (int mt = 0; mt < 2; mt++) {
        int r0 = mbase + wm * 32 + mt * 16 + g;
        int r1 = r0 + 8;
        #pragma unroll
        for (int nt = 0; nt < 4; nt++) {
            int col = wn * 32 + nt * 8 + q * 2;
            if (r0 < N_NODES)
                *(float2*)(C + (size_t)r0 * HID_DIM + col) =
                    make_float2(acc[mt][nt][0], acc[mt][nt][1]);
            if (r1 < N_NODES)
                *(float2*)(C + (size_t)r1 * HID_DIM + col) =
                    make_float2(acc[mt][nt][2], acc[mt][nt][3]);
        }
    }
}

// ---------------- GEMM2: g2[M x 64] = h1 @ W2 (K=128 single tile, no dinv) ----------------
#define SM2_STRIDE 136
#define G2_AH 0
#define G2_AL (128 * SM2_STRIDE * 2)
#define G2_BH (2 * 128 * SM2_STRIDE * 2)
#define G2_BL (G2_BH + 64 * SM2_STRIDE * 2)
#define G2_SMEM (G2_BL + 64 * SM2_STRIDE * 2)

__global__ __launch_bounds__(256)
void gemm2_hmma(float* __restrict__ C) {
    extern __shared__ char smem[];
    const uint32_t sbase = smem_u32(smem);
    const int tid = threadIdx.x, lane = tid & 31, wid = tid >> 5;
    const int wm = wid >> 1, wn = wid & 1;
    const int mbase = blockIdx.x * 128;

    const int a_r = (lane & 15), a_c = ((lane & 16) >> 1);
    const int b_r = ((lane & 16) >> 1) + (lane & 7), b_c = (lane & 8);

    #pragma unroll
    for (int i = tid; i < 2048; i += 256) {
        int r = i >> 4, c8 = (i & 15) * 8;
        int gr = mbase + r;
        bool ok = gr < N_NODES;
        uint32_t doff = (uint32_t)(r * SM2_STRIDE + c8) * 2;
        size_t soff = (size_t)gr * HID_DIM + c8;
        cp16(sbase + G2_AH + doff, g_h1h + soff, ok);
        cp16(sbase + G2_AL + doff, g_h1l + soff, ok);
    }
    #pragma unroll
    for (int i = tid; i < 1024; i += 256) {
        int n = i >> 4, c8 = (i & 15) * 8;
        uint32_t doff = (uint32_t)(n * SM2_STRIDE + c8) * 2;
        size_t soff = (size_t)n * HID_DIM + c8;
        cp16(sbase + G2_BH + doff, g_W2t_hi + soff, true);
        cp16(sbase + G2_BL + doff, g_W2t_lo + soff, true);
    }
    cp_commit();
    cp_wait_all();
    __syncthreads();

    float acc[2][4][4];
    #pragma unroll
    for (int i = 0; i < 2; i++)
        #pragma unroll
        for (int j = 0; j < 4; j++)
            #pragma unroll
            for (int v = 0; v < 4; v++) acc[i][j][v] = 0.f;

    #pragma unroll
    for (int ks = 0; ks < 8; ks++) {
        const int kk = ks * 16;
        uint32_t ah[2][4], al[2][4], bhf[4][2], blf[4][2];
        #pragma unroll
        for (int mt = 0; mt < 2; mt++) {
            uint32_t ea = (uint32_t)((wm * 32 + mt * 16 + a_r) * SM2_STRIDE + kk + a_c) * 2;
            ldsm_x4(ah[mt][0], ah[mt][1], ah[mt][2], ah[mt][3], sbase + G2_AH + ea);
            ldsm_x4(al[mt][0], al[mt][1], al[mt][2], al[mt][3], sbase + G2_AL + ea);
        }
        #pragma unroll
        for (int pr = 0; pr < 2; pr++) {
            uint32_t eb = (uint32_t)((wn * 32 + pr * 16 + b_r) * SM2_STRIDE + kk + b_c) * 2;
            ldsm_x4(bhf[2*pr][0], bhf[2*pr][1], bhf[2*pr+1][0], bhf[2*pr+1][1], sbase + G2_BH + eb);
            ldsm_x4(blf[2*pr][0], blf[2*pr][1], blf[2*pr+1][0], blf[2*pr+1][1], sbase + G2_BL + eb);
        }
        #pragma unroll
        for (int mt = 0; mt < 2; mt++)
            #pragma unroll
            for (int nt = 0; nt < 4; nt++) {
                mma_bf16(acc[mt][nt], ah[mt], bhf[nt]);
                mma_bf16(acc[mt][nt], ah[mt], blf[nt]);
                mma_bf16(acc[mt][nt], al[mt], bhf[nt]);
            }
    }

    const int g = lane >> 2, q = lane & 3;
    #pragma unroll
    for (int mt = 0; mt < 2; mt++) {
        int r0 = mbase + wm * 32 + mt * 16 + g;
        int r1 = r0 + 8;
        #pragma unroll
        for (int nt = 0; nt < 4; nt++) {
            int col = wn * 32 + nt * 8 + q * 2;
            if (r0 < N_NODES)
                *(float2*)(C + (size_t)r0 * EMB_DIM + col) =
                    make_float2(acc[mt][nt][0], acc[mt][nt][1]);
            if (r1 < N_NODES)
                *(float2*)(C + (size_t)r1 * EMB_DIM + col) =
                    make_float2(acc[mt][nt][2], acc[mt][nt][3]);
        }
    }
}

// ---------------- CSR gather aggregation: warp per node, dinv folded here ----------------
__global__ __launch_bounds__(256)
void aggregate1(const float* __restrict__ g, const float* __restrict__ bias) {
    const int lane = threadIdx.x & 31, wid = threadIdx.x >> 5;
    const int node = blockIdx.x * 8 + wid;
    if (node >= N_NODES) return;
    const float4* g4 = (const float4*)g;

    float di = g_dinv[node];
    float4 v = __ldg(g4 + (size_t)node * 32 + lane);
    float4 s = make_float4(di * v.x, di * v.y, di * v.z, di * v.w);
    int e = g_rowptr[node], end = g_rowptr[node + 1];
    for (; e + 4 <= end; e += 4) {
        int c0 = g_col[e], c1 = g_col[e+1], c2 = g_col[e+2], c3 = g_col[e+3];
        float d0 = __ldg(g_dinv + c0), d1 = __ldg(g_dinv + c1),
              d2 = __ldg(g_dinv + c2), d3 = __ldg(g_dinv + c3);
        float4 v0 = __ldg(g4 + (size_t)c0 * 32 + lane);
        float4 v1 = __ldg(g4 + (size_t)c1 * 32 + lane);
        float4 v2 = __ldg(g4 + (size_t)c2 * 32 + lane);
        float4 v3 = __ldg(g4 + (size_t)c3 * 32 + lane);
        s.x += d0 * v0.x + d1 * v1.x + d2 * v2.x + d3 * v3.x;
        s.y += d0 * v0.y + d1 * v1.y + d2 * v2.y + d3 * v3.y;
        s.z += d0 * v0.z + d1 * v1.z + d2 * v2.z + d3 * v3.z;
        s.w += d0 * v0.w + d1 * v1.w + d2 * v2.w + d3 * v3.w;
    }
    for (; e < end; e++) {
        int c = g_col[e];
        float d = __ldg(g_dinv + c);
        float4 w = __ldg(g4 + (size_t)c * 32 + lane);
        s.x += d * w.x; s.y += d * w.y; s.z += d * w.z; s.w += d * w.w;
    }
    float4 b = __ldg((const float4*)bias + lane);
    float o0 = fmaxf(di * s.x + b.x, 0.f), o1 = fmaxf(di * s.y + b.y, 0.f);
    float o2 = fmaxf(di * s.z + b.z, 0.f), o3 = fmaxf(di * s.w + b.w, 0.f);
    __nv_bfloat16 h0 = __float2bfloat16(o0), h1 = __float2bfloat16(o1),
                  h2 = __float2bfloat16(o2), h3 = __float2bfloat16(o3);
    uint2 H = make_uint2(pkh(h0, h1), pkh(h2, h3));
    uint2 L = make_uint2(
        pkh(__float2bfloat16(o0 - __bfloat162float(h0)),
            __float2bfloat16(o1 - __bfloat162float(h1))),
        pkh(__float2bfloat16(o2 - __bfloat162float(h2)),
            __float2bfloat16(o3 - __bfloat162float(h3))));
    ((uint2*)g_h1h)[(size_t)node * 32 + lane] = H;
    ((uint2*)g_h1l)[(size_t)node * 32 + lane] = L;
}
__global__ __launch_bounds__(256)
void aggregate2(const float* __restrict__ g, const float* __restrict__ bias,
                float* __restrict__ out) {
    const int lane = threadIdx.x & 31, wid = threadIdx.x >> 5;
    const int node = blockIdx.x * 8 + wid;
    if (node >= N_NODES) return;
    const float2* g2 = (const float2*)g;

    float di = g_dinv[node];
    float2 v = __ldg(g2 + (size_t)node * 32 + lane);
    float2 s = make_float2(di * v.x, di * v.y);
    int e = g_rowptr[node], end = g_rowptr[node + 1];
    for (; e + 4 <= end; e += 4) {
        int c0 = g_col[e], c1 = g_col[e+1], c2 = g_col[e+2], c3 = g_col[e+3];
        float d0 = __ldg(g_dinv + c0), d1 = __ldg(g_dinv + c1),
              d2 = __ldg(g_dinv + c2), d3 = __ldg(g_dinv + c3);
        float2 v0 = __ldg(g2 + (size_t)c0 * 32 + lane);
        float2 v1 = __ldg(g2 + (size_t)c1 * 32 + lane);
        float2 v2 = __ldg(g2 + (size_t)c2 * 32 + lane);
        float2 v3 = __ldg(g2 + (size_t)c3 * 32 + lane);
        s.x += d0 * v0.x + d1 * v1.x + d2 * v2.x + d3 * v3.x;
        s.y += d0 * v0.y + d1 * v1.y + d2 * v2.y + d3 * v3.y;
    }
    for (; e < end; e++) {
        int c = g_col[e];
        float d = __ldg(g_dinv + c);
        float2 w = __ldg(g2 + (size_t)c * 32 + lane);
        s.x += d * w.x; s.y += d * w.y;
    }
    float2 b = __ldg((const float2*)bias + lane);
    ((float2*)out)[(size_t)node * 32 + lane] = make_float2(di * s.x + b.x, di * s.y + b.y);
}

// ---------------- launch ----------------
extern "C" void kernel_launch(void* const* d_in, const int* in_sizes, int n_in,
                              void* d_out, int out_size) {
    const float* x  = (const float*)d_in[0];
    const int*   ei = (const int*)  d_in[1];
    const float* W1 = (const float*)d_in[2];
    const float* b1 = (const float*)d_in[3];
    const float* W2 = (const float*)d_in[4];
    const float* b2 = (const float*)d_in[5];
    float* out = (float*)d_out;

    const int4* src4 = (const int4*)ei;
    const int4* dst4 = (const int4*)(ei + N_EDGES);

    float *p_g1 = nullptr, *p_g2 = nullptr;
    cudaGetSymbolAddress((void**)&p_g1, g_g1);
    cudaGetSymbolAddress((void**)&p_g2, g_g2);

    static cudaStream_t s2 = nullptr;
    static cudaEvent_t ev_fork = nullptr, ev_join = nullptr;
    static bool init_done = false;
    if (!init_done) {
        cudaFuncSetAttribute(gemm1_hmma, cudaFuncAttributeMaxDynamicSharedMemorySize, G1_SMEM);
        cudaFuncSetAttribute(gemm2_hmma, cudaFuncAttributeMaxDynamicSharedMemorySize, G2_SMEM);
        cudaStreamCreateWithFlags(&s2, cudaStreamNonBlocking);
        cudaEventCreateWithFlags(&ev_fork, cudaEventDisableTiming);
        cudaEventCreateWithFlags(&ev_join, cudaEventDisableTiming);
        init_done = true;
    }

    // fork: CSR build + W2 convert on side stream, concurrent with W1 convert + gemm1
    cudaEventRecord(ev_fork, 0);
    cudaStreamWaitEvent(s2, ev_fork, 0);

    k_zero_indeg<<<(N_NODES + 255) / 256, 256, 0, s2>>>();
    k_hist<<<(N_EDGES / 4 + 255) / 256, 256, 0, s2>>>(dst4);
    k_scan<<<1, 1024, 0, s2>>>();
    k_fill<<<(N_EDGES / 4 + 255) / 256, 256, 0, s2>>>(src4, dst4);
    k_convert_W2<<<(EMB_DIM * HID_DIM + 255) / 256, 256, 0, s2>>>(W2);
    cudaEventRecord(ev_join, s2);

    k_convert_W<<<dim3(KPAD / 32, HID_DIM / 32), dim3(32, 8)>>>(W1);

    const int mblocks = (N_NODES + 127) / 128;
    gemm1_hmma<<<mblocks, G1_THREADS, G1_SMEM>>>(x, p_g1);

    // join: aggregation needs CSR + dinv (and gemm2 needs W2 converts)
    cudaStreamWaitEvent(0, ev_join, 0);
    aggregate1<<<(N_NODES + 7) / 8, 256>>>(p_g1, b1);
    gemm2_hmma<<<mblocks, 256, G2_SMEM>>>(p_g2);
    aggregate2<<<(N_NODES + 7) / 8, 256>>>(p_g2, b2, out);
}

// round 13
// speedup vs baseline: 1.9350x; 1.0727x over previous
#include <cuda_runtime.h>
#include <cuda_bf16.h>
#include <cstdint>

#define N_NODES 100000
#define N_EDGES 1600000
#define IN_DIM 1433
#define HID_DIM 128
#define EMB_DIM 64
#define KPAD 1472          // 23 * 64
#define KCHUNKS 23

// ---------------- scratch (static device globals; no cudaMalloc allowed) ----------------
__device__ float g_g1[(size_t)N_NODES * HID_DIM];
__device__ __nv_bfloat16 g_h1h[(size_t)N_NODES * HID_DIM];
__device__ __nv_bfloat16 g_h1l[(size_t)N_NODES * HID_DIM];
__device__ float g_g2[(size_t)N_NODES * EMB_DIM];
__device__ int   g_indeg[N_NODES];
__device__ int   g_rowptr[N_NODES + 1];
__device__ int   g_cursor[N_NODES];
__device__ int   g_col[N_EDGES];
__device__ float g_dinv[N_NODES];
__device__ __nv_bfloat16 g_Wt_hi[HID_DIM * KPAD];    // W1^T split-high, [128][KPAD]
__device__ __nv_bfloat16 g_Wt_lo[HID_DIM * KPAD];
__device__ __nv_bfloat16 g_W2t_hi[EMB_DIM * HID_DIM]; // W2^T split, [64][128]
__device__ __nv_bfloat16 g_W2t_lo[EMB_DIM * HID_DIM];

// ---------------- portable PTX helpers ----------------
__device__ __forceinline__ uint32_t smem_u32(const void* p) {
    uint32_t a;
    asm("{ .reg .u64 t; cvta.to.shared.u64 t, %1; cvt.u32.u64 %0, t; }" : "=r"(a) : "l"(p));
    return a;
}
__device__ __forceinline__ void ldsm_x4(uint32_t& r0, uint32_t& r1, uint32_t& r2, uint32_t& r3,
                                        uint32_t addr) {
    asm volatile("ldmatrix.sync.aligned.m8n8.x4.shared.b16 {%0,%1,%2,%3}, [%4];"
                 : "=r"(r0), "=r"(r1), "=r"(r2), "=r"(r3) : "r"(addr));
}
__device__ __forceinline__ void mma_bf16(float* d, const uint32_t* a, const uint32_t* b) {
    asm volatile(
        "mma.sync.aligned.m16n8k16.row.col.f32.bf16.bf16.f32 "
        "{%0,%1,%2,%3}, {%4,%5,%6,%7}, {%8,%9}, {%0,%1,%2,%3};"
        : "+f"(d[0]), "+f"(d[1]), "+f"(d[2]), "+f"(d[3])
        : "r"(a[0]), "r"(a[1]), "r"(a[2]), "r"(a[3]), "r"(b[0]), "r"(b[1]));
}
__device__ __forceinline__ void cp16(uint32_t dst, const void* src, bool valid) {
    int sz = valid ? 16 : 0;
    asm volatile("cp.async.cg.shared.global [%0], [%1], 16, %2;"
                 :: "r"(dst), "l"(src), "r"(sz) : "memory");
}
__device__ __forceinline__ void cp4(uint32_t dst, const void* src, bool valid) {
    int sz = valid ? 4 : 0;
    asm volatile("cp.async.ca.shared.global [%0], [%1], 4, %2;"
                 :: "r"(dst), "l"(src), "r"(sz) : "memory");
}
__device__ __forceinline__ void cp_commit() { asm volatile("cp.async.commit_group;" ::: "memory"); }
__device__ __forceinline__ void cp_wait_all() { asm volatile("cp.async.wait_group 0;" ::: "memory"); }
__device__ __forceinline__ uint32_t pkh(__nv_bfloat16 a, __nv_bfloat16 b) {
    __nv_bfloat162 t; t.x = a; t.y = b;
    return *(uint32_t*)&t;
}

// ---------------- CSR build ----------------
__global__ void k_zero_indeg() {
    int i = blockIdx.x * blockDim.x + threadIdx.x;
    if (i < N_NODES) g_indeg[i] = 0;
}
__global__ void k_hist(const int4* __restrict__ dst4) {
    int i = blockIdx.x * blockDim.x + threadIdx.x;
    if (i < N_EDGES / 4) {
        int4 d = __ldg(dst4 + i);
        atomicAdd(&g_indeg[d.x], 1);
        atomicAdd(&g_indeg[d.y], 1);
        atomicAdd(&g_indeg[d.z], 1);
        atomicAdd(&g_indeg[d.w], 1);
    }
}
__global__ void k_scan() {
    __shared__ int wsum[32];
    __shared__ int s_carry;
    const int tid = threadIdx.x, lane = tid & 31, wid = tid >> 5;
    if (tid == 0) s_carry = 0;
    __syncthreads();
    for (int base = 0; base < N_NODES; base += 1024) {
        int i = base + tid;
        int v = (i < N_NODES) ? g_indeg[i] : 0;
        int x = v;
        #pragma unroll
        for (int off = 1; off < 32; off <<= 1) {
            int t = __shfl_up_sync(0xFFFFFFFF, x, off);
            if (lane >= off) x += t;
        }
        if (lane == 31) wsum[wid] = x;
        __syncthreads();
        if (wid == 0) {
            int w = wsum[lane];
            #pragma unroll
            for (int off = 1; off < 32; off <<= 1) {
                int t = __shfl_up_sync(0xFFFFFFFF, w, off);
                if (lane >= off) w += t;
            }
            wsum[lane] = w;
        }
        __syncthreads();
        int incl = x + (wid > 0 ? wsum[wid - 1] : 0) + s_carry;
        if (i < N_NODES) {
            int rp = incl - v;
            g_rowptr[i] = rp;
            g_cursor[i] = rp;
            g_dinv[i]   = rsqrtf((float)(v + 1));
        }
        __syncthreads();
        if (tid == 0) s_carry += wsum[31];
        __syncthreads();
    }
    if (tid == 0) g_rowptr[N_NODES] = N_EDGES;
}
__global__ void k_fill(const int4* __restrict__ src4, const int4* __restrict__ dst4) {
    int i = blockIdx.x * blockDim.x + threadIdx.x;
    if (i < N_EDGES / 4) {
        int4 s = __ldg(src4 + i);
        int4 d = __ldg(dst4 + i);
        g_col[atomicAdd(&g_cursor[d.x], 1)] = s.x;
        g_col[atomicAdd(&g_cursor[d.y], 1)] = s.y;
        g_col[atomicAdd(&g_cursor[d.z], 1)] = s.z;
        g_col[atomicAdd(&g_cursor[d.w], 1)] = s.w;
    }
}

// ---------------- weight transpose + bf16 split (smem tiled) ----------------
__global__ void k_convert_W(const float* __restrict__ W1) {
    __shared__ float t[32][33];
    int k0 = blockIdx.x * 32, n0 = blockIdx.y * 32;
    #pragma unroll
    for (int j = threadIdx.y; j < 32; j += 8) {
        int k = k0 + j, n = n0 + threadIdx.x;
        t[j][threadIdx.x] = (k < IN_DIM) ? __ldg(W1 + (size_t)k * HID_DIM + n) : 0.f;
    }
    __syncthreads();
    #pragma unroll
    for (int j = threadIdx.y; j < 32; j += 8) {
        int n = n0 + j, k = k0 + threadIdx.x;
        float v = t[threadIdx.x][j];
        __nv_bfloat16 h = __float2bfloat16(v);
        size_t o = (size_t)n * KPAD + k;
        g_Wt_hi[o] = h;
        g_Wt_lo[o] = __float2bfloat16(v - __bfloat162float(h));
    }
}
__global__ void k_convert_W2(const float* __restrict__ W2) {
    int idx = blockIdx.x * blockDim.x + threadIdx.x;
    if (idx < EMB_DIM * HID_DIM) {
        int n = idx / HID_DIM, k = idx % HID_DIM;
        float v = W2[(size_t)k * EMB_DIM + n];
        __nv_bfloat16 h = __float2bfloat16(v);
        g_W2t_hi[idx] = h;
        g_W2t_lo[idx] = __float2bfloat16(v - __bfloat162float(h));
    }
}

// ---------------- GEMM1: C[M x 128] = X @ W1  (R9-proven pipeline, 512 threads) ----------------
#define SM_STRIDE 72   // bf16 elems per row (144B): conflict-free ldmatrix
#define G1_XF0 0
#define G1_XF1 32768
#define G1_AH  65536
#define G1_AL  83968
#define G1_B0  102400
#define G1_BSTG 18432
#define G1_BL0 (G1_B0 + 2 * G1_BSTG)
#define G1_SMEM (G1_BL0 + 2 * G1_BSTG)   /* 176128 */
#define G1_THREADS 512

__global__ __launch_bounds__(G1_THREADS)
void gemm1_hmma(const float* __restrict__ X, float* __restrict__ C) {
    extern __shared__ char smem[];
    const uint32_t sbase = smem_u32(smem);
    const int tid = threadIdx.x, lane = tid & 31, wid = tid >> 5;
    const int wm = wid >> 2, wn = wid & 3;   // 4 x 4 warps, warp tile 32 x 32
    const int mbase = blockIdx.x * 128;

    const int a_r = (lane & 15), a_c = ((lane & 16) >> 1);
    const int b_r = ((lane & 16) >> 1) + (lane & 7), b_c = (lane & 8);

    float acc[2][4][4];
    #pragma unroll
    for (int i = 0; i < 2; i++)
        #pragma unroll
        for (int j = 0; j < 4; j++)
            #pragma unroll
            for (int v = 0; v < 4; v++) acc[i][j][v] = 0.f;

    auto issue = [&](int kc, int buf) {
        const int k0 = kc * 64;
        uint32_t xdst = sbase + (buf ? G1_XF1 : G1_XF0);
        #pragma unroll
        for (int i = tid; i < 8192; i += G1_THREADS) {
            int r = i >> 6, kp = i & 63;
            int gr = mbase + r, gk = k0 + kp;
            cp4(xdst + (uint32_t)i * 4, X + (size_t)gr * IN_DIM + gk,
                (gr < N_NODES) && (gk < IN_DIM));
        }
        uint32_t bh = sbase + G1_B0 + buf * G1_BSTG;
        uint32_t bl = sbase + G1_BL0 + buf * G1_BSTG;
        #pragma unroll
        for (int i = tid; i < 1024; i += G1_THREADS) {
            int n = i >> 3, c8 = (i & 7) * 8;
            uint32_t doff = (uint32_t)(n * SM_STRIDE + c8) * 2;
            size_t soff = (size_t)n * KPAD + k0 + c8;
            cp16(bh + doff, g_Wt_hi + soff, true);
            cp16(bl + doff, g_Wt_lo + soff, true);
        }
    };

    issue(0, 0);
    cp_commit();

    for (int kc = 0; kc < KCHUNKS; kc++) {
        const int buf = kc & 1;
        cp_wait_all();
        __syncthreads();
        if (kc + 1 < KCHUNKS) { issue(kc + 1, buf ^ 1); cp_commit(); }

        // ---- split fp32 -> hi/lo bf16 (smem -> smem, separate buffers) ----
        {
            const float4* xf = (const float4*)(smem + (buf ? G1_XF1 : G1_XF0));
            #pragma unroll
            for (int i = tid; i < 2048; i += G1_THREADS) {
                float4 v = xf[i];
                int r = i >> 4, kp4 = (i & 15) * 4;
                __nv_bfloat16 h0 = __float2bfloat16(v.x), h1 = __float2bfloat16(v.y);
                __nv_bfloat16 h2 = __float2bfloat16(v.z), h3 = __float2bfloat16(v.w);
                __nv_bfloat16 l0 = __float2bfloat16(v.x - __bfloat162float(h0));
                __nv_bfloat16 l1 = __float2bfloat16(v.y - __bfloat162float(h1));
                __nv_bfloat16 l2 = __float2bfloat16(v.z - __bfloat162float(h2));
                __nv_bfloat16 l3 = __float2bfloat16(v.w - __bfloat162float(h3));
                uint32_t off = (uint32_t)(r * SM_STRIDE + kp4) * 2;
                *(uint2*)(smem + G1_AH + off) = make_uint2(pkh(h0, h1), pkh(h2, h3));
                *(uint2*)(smem + G1_AL + off) = make_uint2(pkh(l0, l1), pkh(l2, l3));
            }
        }
        __syncthreads();

        const uint32_t BH = sbase + G1_B0 + buf * G1_BSTG;
        const uint32_t BL = sbase + G1_BL0 + buf * G1_BSTG;
        #pragma unroll
        for (int ks = 0; ks < 4; ks++) {
            const int kk = ks * 16;
            uint32_t ah[2][4], al[2][4], bhf[4][2], blf[4][2];
            #pragma unroll
            for (int mt = 0; mt < 2; mt++) {
                uint32_t ea = (uint32_t)((wm * 32 + mt * 16 + a_r) * SM_STRIDE + kk + a_c) * 2;
                ldsm_x4(ah[mt][0], ah[mt][1], ah[mt][2], ah[mt][3], sbase + G1_AH + ea);
                ldsm_x4(al[mt][0], al[mt][1], al[mt][2], al[mt][3], sbase + G1_AL + ea);
            }
            #pragma unroll
            for (int pr = 0; pr < 2; pr++) {
                uint32_t eb = (uint32_t)((wn * 32 + pr * 16 + b_r) * SM_STRIDE + kk + b_c) * 2;
                ldsm_x4(bhf[2*pr][0], bhf[2*pr][1], bhf[2*pr+1][0], bhf[2*pr+1][1], BH + eb);
                ldsm_x4(blf[2*pr][0], blf[2*pr][1], blf[2*pr+1][0], blf[2*pr+1][1], BL + eb);
            }
            #pragma unroll
            for (int mt = 0; mt < 2; mt++)
                #pragma unroll
                for (int nt = 0; nt < 4; nt++) {
                    mma_bf16(acc[mt][nt], ah[mt], bhf[nt]);
                    mma_bf16(acc[mt][nt], ah[mt], blf[nt]);
                    mma_bf16(acc[mt][nt], al[mt], bhf[nt]);
                }
        }
        __syncthreads();
    }

    const int g = lane >> 2, q = lane & 3;
    #pragma unroll
    for (int mt = 0; mt < 2; mt++) {
        int r0 = mbase + wm * 32 + mt * 16 + g;
        int r1 = r0 + 8;
        #pragma unroll
        for (int nt = 0; nt < 4; nt++) {
            int col = wn * 32 + nt * 8 + q * 2;
            if (r0 < N_NODES)
                *(float2*)(C + (size_t)r0 * HID_DIM + col) =
                    make_float2(acc[mt][nt][0], acc[mt][nt][1]);
            if (r1 < N_NODES)
                *(float2*)(C + (size_t)r1 * HID_DIM + col) =
                    make_float2(acc[mt][nt][2], acc[mt][nt][3]);
        }
    }
}

// ---------------- GEMM2: g2[M x 64] = h1 @ W2 (K=128 single tile, no dinv) ----------------
#define SM2_STRIDE 136
#define G2_AH 0
#define G2_AL (128 * SM2_STRIDE * 2)
#define G2_BH (2 * 128 * SM2_STRIDE * 2)
#define G2_BL (G2_BH + 64 * SM2_STRIDE * 2)
#define G2_SMEM (G2_BL + 64 * SM2_STRIDE * 2)

__global__ __launch_bounds__(256)
void gemm2_hmma(float* __restrict__ C) {
    extern __shared__ char smem[];
    const uint32_t sbase = smem_u32(smem);
    const int tid = threadIdx.x, lane = tid & 31, wid = tid >> 5;
    const int wm = wid >> 1, wn = wid & 1;
    const int mbase = blockIdx.x * 128;

    const int a_r = (lane & 15), a_c = ((lane & 16) >> 1);
    const int b_r = ((lane & 16) >> 1) + (lane & 7), b_c = (lane & 8);

    #pragma unroll
    for (int i = tid; i < 2048; i += 256) {
        int r = i >> 4, c8 = (i & 15) * 8;
        int gr = mbase + r;
        bool ok = gr < N_NODES;
        uint32_t doff = (uint32_t)(r * SM2_STRIDE + c8) * 2;
        size_t soff = (size_t)gr * HID_DIM + c8;
        cp16(sbase + G2_AH + doff, g_h1h + soff, ok);
        cp16(sbase + G2_AL + doff, g_h1l + soff, ok);
    }
    #pragma unroll
    for (int i = tid; i < 1024; i += 256) {
        int n = i >> 4, c8 = (i & 15) * 8;
        uint32_t doff = (uint32_t)(n * SM2_STRIDE + c8) * 2;
        size_t soff = (size_t)n * HID_DIM + c8;
        cp16(sbase + G2_BH + doff, g_W2t_hi + soff, true);
        cp16(sbase + G2_BL + doff, g_W2t_lo + soff, true);
    }
    cp_commit();
    cp_wait_all();
    __syncthreads();

    float acc[2][4][4];
    #pragma unroll
    for (int i = 0; i < 2; i++)
        #pragma unroll
        for (int j = 0; j < 4; j++)
            #pragma unroll
            for (int v = 0; v < 4; v++) acc[i][j][v] = 0.f;

    #pragma unroll
    for (int ks = 0; ks < 8; ks++) {
        const int kk = ks * 16;
        uint32_t ah[2][4], al[2][4], bhf[4][2], blf[4][2];
        #pragma unroll
        for (int mt = 0; mt < 2; mt++) {
            uint32_t ea = (uint32_t)((wm * 32 + mt * 16 + a_r) * SM2_STRIDE + kk + a_c) * 2;
            ldsm_x4(ah[mt][0], ah[mt][1], ah[mt][2], ah[mt][3], sbase + G2_AH + ea);
            ldsm_x4(al[mt][0], al[mt][1], al[mt][2], al[mt][3], sbase + G2_AL + ea);
        }
        #pragma unroll
        for (int pr = 0; pr < 2; pr++) {
            uint32_t eb = (uint32_t)((wn * 32 + pr * 16 + b_r) * SM2_STRIDE + kk + b_c) * 2;
            ldsm_x4(bhf[2*pr][0], bhf[2*pr][1], bhf[2*pr+1][0], bhf[2*pr+1][1], sbase + G2_BH + eb);
            ldsm_x4(blf[2*pr][0], blf[2*pr][1], blf[2*pr+1][0], blf[2*pr+1][1], sbase + G2_BL + eb);
        }
        #pragma unroll
        for (int mt = 0; mt < 2; mt++)
            #pragma unroll
            for (int nt = 0; nt < 4; nt++) {
                mma_bf16(acc[mt][nt], ah[mt], bhf[nt]);
                mma_bf16(acc[mt][nt], ah[mt], blf[nt]);
                mma_bf16(acc[mt][nt], al[mt], bhf[nt]);
            }
    }

    const int g = lane >> 2, q = lane & 3;
    #pragma unroll
    for (int mt = 0; mt < 2; mt++) {
        int r0 = mbase + wm * 32 + mt * 16 + g;
        int r1 = r0 + 8;
        #pragma unroll
        for (int nt = 0; nt < 4; nt++) {
            int col = wn * 32 + nt * 8 + q * 2;
            if (r0 < N_NODES)
                *(float2*)(C + (size_t)r0 * EMB_DIM + col) =
                    make_float2(acc[mt][nt][0], acc[mt][nt][1]);
            if (r1 < N_NODES)
                *(float2*)(C + (size_t)r1 * EMB_DIM + col) =
                    make_float2(acc[mt][nt][2], acc[mt][nt][3]);
        }
    }
}

// ---------------- CSR gather aggregation: warp per node, dinv folded here ----------------
__global__ __launch_bounds__(256)
void aggregate1(const float* __restrict__ g, const float* __restrict__ bias) {
    const int lane = threadIdx.x & 31, wid = threadIdx.x >> 5;
    const int node = blockIdx.x * 8 + wid;
    if (node >= N_NODES) return;
    const float4* g4 = (const float4*)g;

    float di = g_dinv[node];
    float4 v = __ldg(g4 + (size_t)node * 32 + lane);
    float4 s = make_float4(di * v.x, di * v.y, di * v.z, di * v.w);
    int e = g_rowptr[node], end = g_rowptr[node + 1];
    for (; e + 4 <= end; e += 4) {
        int c0 = g_col[e], c1 = g_col[e+1], c2 = g_col[e+2], c3 = g_col[e+3];
        float d0 = __ldg(g_dinv + c0), d1 = __ldg(g_dinv + c1),
              d2 = __ldg(g_dinv + c2), d3 = __ldg(g_dinv + c3);
        float4 v0 = __ldg(g4 + (size_t)c0 * 32 + lane);
        float4 v1 = __ldg(g4 + (size_t)c1 * 32 + lane);
        float4 v2 = __ldg(g4 + (size_t)c2 * 32 + lane);
        float4 v3 = __ldg(g4 + (size_t)c3 * 32 + lane);
        s.x += d0 * v0.x + d1 * v1.x + d2 * v2.x + d3 * v3.x;
        s.y += d0 * v0.y + d1 * v1.y + d2 * v2.y + d3 * v3.y;
        s.z += d0 * v0.z + d1 * v1.z + d2 * v2.z + d3 * v3.z;
        s.w += d0 * v0.w + d1 * v1.w + d2 * v2.w + d3 * v3.w;
    }
    for (; e < end; e++) {
        int c = g_col[e];
        float d = __ldg(g_dinv + c);
        float4 w = __ldg(g4 + (size_t)c * 32 + lane);
        s.x += d * w.x; s.y += d * w.y; s.z += d * w.z; s.w += d * w.w;
    }
    float4 b = __ldg((const float4*)bias + lane);
    float o0 = fmaxf(di * s.x + b.x, 0.f), o1 = fmaxf(di * s.y + b.y, 0.f);
    float o2 = fmaxf(di * s.z + b.z, 0.f), o3 = fmaxf(di * s.w + b.w, 0.f);
    __nv_bfloat16 h0 = __float2bfloat16(o0), h1 = __float2bfloat16(o1),
                  h2 = __float2bfloat16(o2), h3 = __float2bfloat16(o3);
    uint2 H = make_uint2(pkh(h0, h1), pkh(h2, h3));
    uint2 L = make_uint2(
        pkh(__float2bfloat16(o0 - __bfloat162float(h0)),
            __float2bfloat16(o1 - __bfloat162float(h1))),
        pkh(__float2bfloat16(o2 - __bfloat162float(h2)),
            __float2bfloat16(o3 - __bfloat162float(h3))));
    ((uint2*)g_h1h)[(size_t)node * 32 + lane] = H;
    ((uint2*)g_h1l)[(size_t)node * 32 + lane] = L;
}
__global__ __launch_bounds__(256)
void aggregate2(const float* __restrict__ g, const float* __restrict__ bias,
                float* __restrict__ out) {
    const int lane = threadIdx.x & 31, wid = threadIdx.x >> 5;
    const int node = blockIdx.x * 8 + wid;
    if (node >= N_NODES) return;
    const float2* g2 = (const float2*)g;

    float di = g_dinv[node];
    float2 v = __ldg(g2 + (size_t)node * 32 + lane);
    float2 s = make_float2(di * v.x, di * v.y);
    int e = g_rowptr[node], end = g_rowptr[node + 1];
    for (; e + 4 <= end; e += 4) {
        int c0 = g_col[e], c1 = g_col[e+1], c2 = g_col[e+2], c3 = g_col[e+3];
        float d0 = __ldg(g_dinv + c0), d1 = __ldg(g_dinv + c1),
              d2 = __ldg(g_dinv + c2), d3 = __ldg(g_dinv + c3);
        float2 v0 = __ldg(g2 + (size_t)c0 * 32 + lane);
        float2 v1 = __ldg(g2 + (size_t)c1 * 32 + lane);
        float2 v2 = __ldg(g2 + (size_t)c2 * 32 + lane);
        float2 v3 = __ldg(g2 + (size_t)c3 * 32 + lane);
        s.x += d0 * v0.x + d1 * v1.x + d2 * v2.x + d3 * v3.x;
        s.y += d0 * v0.y + d1 * v1.y + d2 * v2.y + d3 * v3.y;
    }
    for (; e < end; e++) {
        int c = g_col[e];
        float d = __ldg(g_dinv + c);
        float2 w = __ldg(g2 + (size_t)c * 32 + lane);
        s.x += d * w.x; s.y += d * w.y;
    }
    float2 b = __ldg((const float2*)bias + lane);
    ((float2*)out)[(size_t)node * 32 + lane] = make_float2(di * s.x + b.x, di * s.y + b.y);
}

// ---------------- launch ----------------
extern "C" void kernel_launch(void* const* d_in, const int* in_sizes, int n_in,
                              void* d_out, int out_size) {
    const float* x  = (const float*)d_in[0];
    const int*   ei = (const int*)  d_in[1];
    const float* W1 = (const float*)d_in[2];
    const float* b1 = (const float*)d_in[3];
    const float* W2 = (const float*)d_in[4];
    const float* b2 = (const float*)d_in[5];
    float* out = (float*)d_out;

    const int4* src4 = (const int4*)ei;
    const int4* dst4 = (const int4*)(ei + N_EDGES);

    float *p_g1 = nullptr, *p_g2 = nullptr;
    cudaGetSymbolAddress((void**)&p_g1, g_g1);
    cudaGetSymbolAddress((void**)&p_g2, g_g2);

    static cudaStream_t s2 = nullptr;
    static cudaEvent_t ev_fork = nullptr, ev_join = nullptr;
    static bool init_done = false;
    if (!init_done) {
        cudaFuncSetAttribute(gemm1_hmma, cudaFuncAttributeMaxDynamicSharedMemorySize, G1_SMEM);
        cudaFuncSetAttribute(gemm2_hmma, cudaFuncAttributeMaxDynamicSharedMemorySize, G2_SMEM);
        cudaStreamCreateWithFlags(&s2, cudaStreamNonBlocking);
        cudaEventCreateWithFlags(&ev_fork, cudaEventDisableTiming);
        cudaEventCreateWithFlags(&ev_join, cudaEventDisableTiming);
        init_done = true;
    }

    // fork: CSR build + W2 convert on side stream, concurrent with W1 convert + gemm1
    cudaEventRecord(ev_fork, 0);
    cudaStreamWaitEvent(s2, ev_fork, 0);

    k_zero_indeg<<<(N_NODES + 255) / 256, 256, 0, s2>>>();
    k_hist<<<(N_EDGES / 4 + 255) / 256, 256, 0, s2>>>(dst4);
    k_scan<<<1, 1024, 0, s2>>>();
    k_fill<<<(N_EDGES / 4 + 255) / 256, 256, 0, s2>>>(src4, dst4);
    k_convert_W2<<<(EMB_DIM * HID_DIM + 255) / 256, 256, 0, s2>>>(W2);
    cudaEventRecord(ev_join, s2);

    k_convert_W<<<dim3(KPAD / 32, HID_DIM / 32), dim3(32, 8)>>>(W1);

    const int mblocks = (N_NODES + 127) / 128;
    gemm1_hmma<<<mblocks, G1_THREADS, G1_SMEM>>>(x, p_g1);

    // join: aggregation needs CSR + dinv (and gemm2 needs W2 converts)
    cudaStreamWaitEvent(0, ev_join, 0);
    aggregate1<<<(N_NODES + 7) / 8, 256>>>(p_g1, b1);
    gemm2_hmma<<<mblocks, 256, G2_SMEM>>>(p_g2);
    aggregate2<<<(N_NODES + 7) / 8, 256>>>(p_g2, b2, out);
}